// round 12
// baseline (speedup 1.0000x reference)
#include <cuda_runtime.h>
#include <cuda_bf16.h>
#include <cstdint>
#include <cstddef>

#define HW 4096
#define B  2

__device__ __align__(128) float g_M [(size_t)B * HW * HW];
__device__ __align__(128) float g_MT[(size_t)B * HW * HW];
// bf16 split features, layout [b][p][2K]: cols [0,K)=hi, [K,2K)=lo (K-major)
__device__ __align__(128) __nv_bfloat16 g_Xs3[(size_t)B * HW * 2048];
__device__ __align__(128) __nv_bfloat16 g_Xt3[(size_t)B * HW * 2048];
__device__ __align__(128) __nv_bfloat16 g_Xs4[(size_t)B * HW * 4096];
__device__ __align__(128) __nv_bfloat16 g_Xt4[(size_t)B * HW * 4096];
__device__ float g_part[4][64][B * HW];
__device__ float g_inorm[4][B * HW];   // 0:src3 1:tgt3 2:src4 3:tgt4

__device__ __forceinline__ uint32_t smem_u32(const void* p) {
    uint32_t a;
    asm("{ .reg .u64 t; cvta.to.shared.u64 t, %1; cvt.u32.u64 %0, t; }" : "=r"(a) : "l"(p));
    return a;
}
#define CP16(dst, src) \
    asm volatile("cp.async.cg.shared.global [%0], [%1], 16;" :: "r"(dst), "l"(src) : "memory")
#define LDMX4(r, addr) \
    asm volatile("ldmatrix.sync.aligned.m8n8.x4.shared.b16 {%0,%1,%2,%3}, [%4];" \
                 : "=r"((r)[0]), "=r"((r)[1]), "=r"((r)[2]), "=r"((r)[3]) : "r"(addr))
#define MMA16816(c, a, b0, b1) \
    asm volatile("mma.sync.aligned.m16n8k16.row.col.f32.bf16.bf16.f32 " \
                 "{%0,%1,%2,%3},{%4,%5,%6,%7},{%8,%9},{%0,%1,%2,%3};" \
                 : "+f"((c)[0]), "+f"((c)[1]), "+f"((c)[2]), "+f"((c)[3]) \
                 : "r"((a)[0]), "r"((a)[1]), "r"((a)[2]), "r"((a)[3]), "r"(b0), "r"(b1))

// ---------------------------------------------------------------------------
// prep (all four tensors, one launch):
// fp32 [b][c][p] -> bf16 split [b][p][2K] + sum-of-squares partials
// ---------------------------------------------------------------------------
__global__ void prep_kernel(const float* __restrict__ f0, const float* __restrict__ f1,
                            const float* __restrict__ f2, const float* __restrict__ f3)
{
    __shared__ __nv_bfloat16 tH[32][34], tL[32][34];
    __shared__ float red[8][32];

    int y = blockIdx.y;
    int slot, cblk;
    const float* f;
    if      (y < 32)  { slot = 0; cblk = y;       f = f0; }
    else if (y < 64)  { slot = 1; cblk = y - 32;  f = f1; }
    else if (y < 128) { slot = 2; cblk = y - 64;  f = f2; }
    else              { slot = 3; cblk = y - 128; f = f3; }
    int K = (slot < 2) ? 1024 : 2048;
    __nv_bfloat16* X = (slot == 0) ? g_Xs3 : (slot == 1) ? g_Xt3 :
                       (slot == 2) ? g_Xs4 : g_Xt4;

    int tx = threadIdx.x, ty = threadIdx.y;
    int p0 = blockIdx.x * 32, c0 = cblk * 32, b = blockIdx.z;
    const float* fb = f + (size_t)b * K * HW;

    float sq = 0.f;
    #pragma unroll
    for (int r = 0; r < 4; r++) {
        int c = c0 + ty + 8 * r;
        float v = fb[(size_t)c * HW + p0 + tx];
        __nv_bfloat16 h = __float2bfloat16_rn(v);
        tH[ty + 8 * r][tx] = h;
        tL[ty + 8 * r][tx] = __float2bfloat16_rn(v - __bfloat162float(h));
        sq = fmaf(v, v, sq);
    }
    red[ty][tx] = sq;
    __syncthreads();
    if (ty == 0) {
        float s = 0.f;
        #pragma unroll
        for (int k = 0; k < 8; k++) s += red[k][tx];
        g_part[slot][cblk][b * HW + p0 + tx] = s;
    }
    int K2 = 2 * K;
    #pragma unroll
    for (int r = 0; r < 4; r++) {
        int p = p0 + ty + 8 * r;
        size_t base = ((size_t)(b * HW + p)) * K2 + c0 + tx;
        X[base]     = tH[tx][ty + 8 * r];
        X[base + K] = tL[tx][ty + 8 * r];
    }
}

__global__ void finalize_norm_kernel()
{
    int idx = blockIdx.x * 256 + threadIdx.x;
    if (idx >= 4 * B * HW) return;
    int slot = idx >> 13, p = idx & (B * HW - 1);
    int nb = (slot < 2) ? 32 : 64;
    float s = 0.f;
    for (int k = 0; k < nb; k++) s += g_part[slot][k][p];
    g_inorm[slot][p] = 1.0f / sqrtf(s + 1e-6f);
}

// ---------------------------------------------------------------------------
// HMMA correlation GEMM (bf16x3), k-chunk 32, 3-stage cp.async ring,
// ONE __syncthreads per chunk. Sub-tile smem layout is k-major 16B chunks:
//   addr(row, kseg) = kseg*2048 + row*16   (kseg = 16B of k, row = 0..127)
// -> no padding (8 KB/subtile), ldmatrix + cp.async stores conflict-free.
// which=0: res3 (K=1024) -> g_M = C
// which=1: res4 (K=2048) -> v = g_M*C; write g_M AND g_MT (smem transpose)
// CTA 128x128, 8 warps (4x2), warp tile 32x64.
// ---------------------------------------------------------------------------
#define SUBT  8192u
#define ST_AH 0u
#define ST_AL SUBT
#define ST_BH (2u * SUBT)
#define ST_BL (3u * SUBT)
#define STAGE (4u * SUBT)          // 32768
#define NSTG  3
#define SMEM_GEMM (NSTG * 32768)   // 98304; epilogue buf 128*129*4=66048 fits

__global__ __launch_bounds__(256, 2) void gemm_hmma_kernel(int which)
{
    extern __shared__ char sm[];
    uint32_t su = smem_u32(sm);

    const int K    = which ? 2048 : 1024;
    const int catW = 2 * K;
    const int slotA = which ? 3 : 1;   // tgt norms (rows j)
    const int slotB = which ? 2 : 0;   // src norms (cols i)
    const __nv_bfloat16* Ap = which ? g_Xt4 : g_Xt3;
    const __nv_bfloat16* Bp = which ? g_Xs4 : g_Xs3;

    int b  = blockIdx.z;
    int i0 = blockIdx.x * 128, j0 = blockIdx.y * 128;
    int tid = threadIdx.x, lane = tid & 31, warp = tid >> 5;
    int wm = warp & 3, wn = warp >> 2;     // j: wm*32, i: wn*64

    const __nv_bfloat16* Ab = Ap + (size_t)(b * HW + j0) * catW;
    const __nv_bfloat16* Bb = Bp + (size_t)(b * HW + i0) * catW;

    // cp.async geometry: idx = tid + 256*q, q in {0,1};
    // kseg = idx>>7 (0..3), row = idx&127  -> warp-linear smem (no store conflicts)
    int row0 = tid & 127,          ks0 = tid >> 7;          // q=0: ksegs 0,1
    int row1 = row0,               ks1 = ks0 + 2;           // q=1: ksegs 2,3
    uint32_t sm0 = (uint32_t)(ks0 * 2048 + row0 * 16);
    uint32_t sm1 = (uint32_t)(ks1 * 2048 + row1 * 16);
    const __nv_bfloat16* gA0 = Ab + (size_t)row0 * catW + ks0 * 8;
    const __nv_bfloat16* gA1 = Ab + (size_t)row1 * catW + ks1 * 8;
    const __nv_bfloat16* gB0 = Bb + (size_t)row0 * catW + ks0 * 8;
    const __nv_bfloat16* gB1 = Bb + (size_t)row1 * catW + ks1 * 8;

    // ldmatrix lane addresses (k-major subtile layout)
    int aRow = wm * 32 + ((lane >> 3) & 1) * 8 + (lane & 7);
    uint32_t aOff = (uint32_t)(aRow * 16 + (lane >> 4) * 2048);          // +ks*4096, +mi*256
    int bRow = wn * 64 + ((lane >> 4) & 1) * 8 + (lane & 7);
    uint32_t bOff = (uint32_t)(bRow * 16 + ((lane >> 3) & 1) * 2048);    // +ks*4096, +np*256

    float acc[2][8][4];
    #pragma unroll
    for (int mi = 0; mi < 2; mi++)
        #pragma unroll
        for (int ni = 0; ni < 8; ni++)
            #pragma unroll
            for (int q = 0; q < 4; q++) acc[mi][ni][q] = 0.f;

    const int nch = K >> 5;

    auto loadStage = [&](int ch, int buf) {
        uint32_t st = su + (uint32_t)buf * STAGE;
        int kel = ch * 32;
        CP16(st + ST_AH + sm0, gA0 + kel);
        CP16(st + ST_AH + sm1, gA1 + kel);
        CP16(st + ST_AL + sm0, gA0 + kel + K);
        CP16(st + ST_AL + sm1, gA1 + kel + K);
        CP16(st + ST_BH + sm0, gB0 + kel);
        CP16(st + ST_BH + sm1, gB1 + kel);
        CP16(st + ST_BL + sm0, gB0 + kel + K);
        CP16(st + ST_BL + sm1, gB1 + kel + K);
        asm volatile("cp.async.commit_group;" ::: "memory");
    };

    loadStage(0, 0);
    loadStage(1, 1);

    int bufC = 0;                       // ch % NSTG
    int bufL = 2;                       // (ch+2) % NSTG
    for (int ch = 0; ch < nch; ch++) {
        if (ch + 1 < nch) asm volatile("cp.async.wait_group 1;" ::: "memory");
        else              asm volatile("cp.async.wait_group 0;" ::: "memory");
        __syncthreads();
        // buffer (ch+2)%3 == (ch-1)%3 was consumed at ch-1; fenced by the sync
        if (ch + 2 < nch) loadStage(ch + 2, bufL);

        uint32_t st = su + (uint32_t)bufC * STAGE;
        #pragma unroll
        for (int ks = 0; ks < 2; ks++) {
            uint32_t ahi[2][4], alo[2][4], br[4][4];
            LDMX4(ahi[0], st + ST_AH + aOff + ks * 4096u);
            LDMX4(ahi[1], st + ST_AH + aOff + ks * 4096u + 256u);
            LDMX4(alo[0], st + ST_AL + aOff + ks * 4096u);
            LDMX4(alo[1], st + ST_AL + aOff + ks * 4096u + 256u);
            #pragma unroll
            for (int np = 0; np < 4; np++)
                LDMX4(br[np], st + ST_BH + bOff + ks * 4096u + np * 256u);
            #pragma unroll
            for (int mi = 0; mi < 2; mi++)
                #pragma unroll
                for (int ni = 0; ni < 8; ni++)
                    MMA16816(acc[mi][ni], ahi[mi],
                             br[ni >> 1][(ni & 1) * 2], br[ni >> 1][(ni & 1) * 2 + 1]);
            #pragma unroll
            for (int mi = 0; mi < 2; mi++)
                #pragma unroll
                for (int ni = 0; ni < 8; ni++)
                    MMA16816(acc[mi][ni], alo[mi],
                             br[ni >> 1][(ni & 1) * 2], br[ni >> 1][(ni & 1) * 2 + 1]);
            #pragma unroll
            for (int np = 0; np < 4; np++)
                LDMX4(br[np], st + ST_BL + bOff + ks * 4096u + np * 256u);
            #pragma unroll
            for (int mi = 0; mi < 2; mi++)
                #pragma unroll
                for (int ni = 0; ni < 8; ni++)
                    MMA16816(acc[mi][ni], ahi[mi],
                             br[ni >> 1][(ni & 1) * 2], br[ni >> 1][(ni & 1) * 2 + 1]);
        }
        bufC = (bufC == NSTG - 1) ? 0 : bufC + 1;
        bufL = (bufL == NSTG - 1) ? 0 : bufL + 1;
    }

    // ------------------- epilogue -------------------
    int rl = wm * 32 + (lane >> 2);         // local j
    int cl = wn * 64 + (lane & 3) * 2;      // local i
    int rj = j0 + rl, ci = i0 + cl;

    float sj[2][2], si[8][2];
    #pragma unroll
    for (int mi = 0; mi < 2; mi++) {
        sj[mi][0] = g_inorm[slotA][b * HW + rj + mi * 16];
        sj[mi][1] = g_inorm[slotA][b * HW + rj + mi * 16 + 8];
    }
    #pragma unroll
    for (int ni = 0; ni < 8; ni++) {
        si[ni][0] = g_inorm[slotB][b * HW + ci + ni * 8];
        si[ni][1] = g_inorm[slotB][b * HW + ci + ni * 8 + 1];
    }

    size_t mbase = (size_t)b * HW * HW;
    if (which == 0) {
        #pragma unroll
        for (int mi = 0; mi < 2; mi++)
            #pragma unroll
            for (int ni = 0; ni < 8; ni++) {
                int r = rj + mi * 16, c = ci + ni * 8;
                float v00 = fmaxf(acc[mi][ni][0] * sj[mi][0] * si[ni][0], 0.f);
                float v01 = fmaxf(acc[mi][ni][1] * sj[mi][0] * si[ni][1], 0.f);
                float v10 = fmaxf(acc[mi][ni][2] * sj[mi][1] * si[ni][0], 0.f);
                float v11 = fmaxf(acc[mi][ni][3] * sj[mi][1] * si[ni][1], 0.f);
                *(float2*)&g_M[mbase + (size_t)r * HW + c]       = make_float2(v00, v01);
                *(float2*)&g_M[mbase + (size_t)(r + 8) * HW + c] = make_float2(v10, v11);
            }
    } else {
        __syncthreads();                    // all loads drained; reuse smem
        float* buf = (float*)sm;            // 128 x 129 floats (66 KB)
        #pragma unroll
        for (int mi = 0; mi < 2; mi++)
            #pragma unroll
            for (int ni = 0; ni < 8; ni++) {
                int r = rj + mi * 16, c = ci + ni * 8;
                int lr = rl + mi * 16, lc = cl + ni * 8;
                float v00 = fmaxf(acc[mi][ni][0] * sj[mi][0] * si[ni][0], 0.f);
                float v01 = fmaxf(acc[mi][ni][1] * sj[mi][0] * si[ni][1], 0.f);
                float v10 = fmaxf(acc[mi][ni][2] * sj[mi][1] * si[ni][0], 0.f);
                float v11 = fmaxf(acc[mi][ni][3] * sj[mi][1] * si[ni][1], 0.f);
                float2* p0 = (float2*)&g_M[mbase + (size_t)r * HW + c];
                float2* p1 = (float2*)&g_M[mbase + (size_t)(r + 8) * HW + c];
                float2 o0 = *p0, o1 = *p1;
                float w00 = o0.x * v00, w01 = o0.y * v01;
                float w10 = o1.x * v10, w11 = o1.y * v11;
                *p0 = make_float2(w00, w01);
                *p1 = make_float2(w10, w11);
                buf[lr * 129 + lc]           = w00;
                buf[lr * 129 + lc + 1]       = w01;
                buf[(lr + 8) * 129 + lc]     = w10;
                buf[(lr + 8) * 129 + lc + 1] = w11;
            }
        __syncthreads();
        #pragma unroll
        for (int it = 0; it < 16; it++) {
            int c = warp * 16 + it;          // local i (column of tile)
            int r = lane * 4;                // local j
            float4 v;
            v.x = buf[(r + 0) * 129 + c];
            v.y = buf[(r + 1) * 129 + c];
            v.z = buf[(r + 2) * 129 + c];
            v.w = buf[(r + 3) * 129 + c];
            *(float4*)&g_MT[mbase + (size_t)(i0 + c) * HW + j0 + r] = v;
        }
    }
}

// ---------------------------------------------------------------------------
// kernel-soft-argmax, both directions in one launch.
// ---------------------------------------------------------------------------
__global__ __launch_bounds__(256)
void soft_argmax_kernel(float* __restrict__ out)
{
    __shared__ float srow[HW];
    __shared__ float gx[64], gy[64];
    __shared__ float wsum[8], wmax[8], wS[8], wSY[8];
    __shared__ int   widx[8];
    __shared__ float s_alpha;
    __shared__ int   s_xs, s_ys;

    int dir = blockIdx.x >> 13;
    int sub = blockIdx.x & 8191;
    int row = sub & (HW - 1);
    int b   = sub >> 12;
    const float* base = dir ? g_M : g_MT;
    float* outG = out + dir * 32768;
    const float4* rp = (const float4*)(base + (size_t)sub * HW);

    int tid = threadIdx.x, warp = tid >> 5, lane = tid & 31;

    #pragma unroll
    for (int q = 0; q < 4; q++) {
        float4 v = rp[q * 256 + tid];
        *(float4*)&srow[(q * 256 + tid) * 4] = v;
    }
    __syncthreads();

    float sumsq = 0.f, vmax = -1.f;
    int imax = 0;
    #pragma unroll
    for (int q = 0; q < 16; q++) {
        int a = q * 256 + tid;
        float v = srow[a];
        sumsq = fmaf(v, v, sumsq);
        if (v > vmax) { vmax = v; imax = a; }
    }
    #pragma unroll
    for (int off = 16; off > 0; off >>= 1) {
        sumsq += __shfl_down_sync(0xffffffffu, sumsq, off);
        float ov = __shfl_down_sync(0xffffffffu, vmax, off);
        int   oi = __shfl_down_sync(0xffffffffu, imax, off);
        if (ov > vmax || (ov == vmax && oi < imax)) { vmax = ov; imax = oi; }
    }
    if (lane == 0) { wsum[warp] = sumsq; wmax[warp] = vmax; widx[warp] = imax; }
    __syncthreads();
    if (tid == 0) {
        float ss = 0.f, vm = -1.f; int im = 0;
        #pragma unroll
        for (int w = 0; w < 8; w++) {
            ss += wsum[w];
            if (wmax[w] > vm || (wmax[w] == vm && widx[w] < im)) { vm = wmax[w]; im = widx[w]; }
        }
        s_alpha = 50.f / sqrtf(ss + 1e-6f);
        s_xs = im & 63;
        s_ys = im >> 6;
    }
    __syncthreads();

    if (tid < 64) {
        float dx = (float)(tid - s_xs);
        gx[tid] = __expf(-dx * dx * 0.02f);
    } else if (tid < 128) {
        float dy = (float)((tid - 64) - s_ys);
        gy[tid - 64] = __expf(-dy * dy * 0.02f);
    }
    __syncthreads();

    float alpha = s_alpha;
    int   xa  = tid & 63;
    float gxv = gx[xa];
    float xn  = fmaf((float)xa, 2.f / 63.f, -1.f);

    float s = 0.f, sy = 0.f;
    #pragma unroll
    for (int q = 0; q < 16; q++) {
        int a  = q * 256 + tid;
        int ya = a >> 6;
        float e = __expf(alpha * gxv * gy[ya] * srow[a]);
        s += e;
        sy = fmaf(e, fmaf((float)ya, 2.f / 63.f, -1.f), sy);
    }
    float sx = s * xn;

    #pragma unroll
    for (int off = 16; off > 0; off >>= 1) {
        s  += __shfl_down_sync(0xffffffffu, s,  off);
        sx += __shfl_down_sync(0xffffffffu, sx, off);
        sy += __shfl_down_sync(0xffffffffu, sy, off);
    }
    if (lane == 0) { wS[warp] = s; wsum[warp] = sx; wSY[warp] = sy; }
    __syncthreads();
    if (tid == 0) {
        float S = 0.f, SX = 0.f, SY = 0.f;
        #pragma unroll
        for (int w = 0; w < 8; w++) { S += wS[w]; SX += wsum[w]; SY += wSY[w]; }
        int yr = row >> 6, xr = row & 63;
        size_t o = ((size_t)(b * 64 + yr) * 64 + xr) * 2;
        outG[o + 0] = SX / S;
        outG[o + 1] = SY / S;
    }
}

// ---------------------------------------------------------------------------
extern "C" void kernel_launch(void* const* d_in, const int* in_sizes, int n_in,
                              void* d_out, int out_size)
{
    const float* src3 = (const float*)d_in[0];
    const float* tgt3 = (const float*)d_in[1];
    const float* src4 = (const float*)d_in[2];
    const float* tgt4 = (const float*)d_in[3];
    float* out = (float*)d_out;

    cudaFuncSetAttribute(gemm_hmma_kernel,
                         cudaFuncAttributeMaxDynamicSharedMemorySize, SMEM_GEMM);

    prep_kernel<<<dim3(HW / 32, 192, B), dim3(32, 8)>>>(src3, tgt3, src4, tgt4);
    finalize_norm_kernel<<<128, 256>>>();

    dim3 gg(HW / 128, HW / 128, B);
    gemm_hmma_kernel<<<gg, 256, SMEM_GEMM>>>(0);   // res3: M  = C3
    gemm_hmma_kernel<<<gg, 256, SMEM_GEMM>>>(1);   // res4: M *= C4, MT written too

    soft_argmax_kernel<<<2 * B * HW, 256>>>(out);  // both directions

    cudaMemsetAsync(out + 16384, 0, 16384 * sizeof(float));
    cudaMemsetAsync(out + 49152, 0, 16384 * sizeof(float));
}

// round 15
// speedup vs baseline: 1.5758x; 1.5758x over previous
#include <cuda_runtime.h>
#include <cuda_bf16.h>
#include <cstdint>
#include <cstddef>

#define HW 4096
#define B  2

__device__ __align__(128) float g_M [(size_t)B * HW * HW];
__device__ __align__(128) float g_MT[(size_t)B * HW * HW];
// bf16 split features, layout [b][p][2K]: cols [0,K)=hi, [K,2K)=lo (K-major)
__device__ __align__(128) __nv_bfloat16 g_Xs3[(size_t)B * HW * 2048];
__device__ __align__(128) __nv_bfloat16 g_Xt3[(size_t)B * HW * 2048];
__device__ __align__(128) __nv_bfloat16 g_Xs4[(size_t)B * HW * 4096];
__device__ __align__(128) __nv_bfloat16 g_Xt4[(size_t)B * HW * 4096];
__device__ float g_part[4][64][B * HW];
__device__ float g_inorm[4][B * HW];   // 0:src3 1:tgt3 2:src4 3:tgt4

__device__ __forceinline__ uint32_t smem_u32(const void* p) {
    uint32_t a;
    asm("{ .reg .u64 t; cvta.to.shared.u64 t, %1; cvt.u32.u64 %0, t; }" : "=r"(a) : "l"(p));
    return a;
}
#define CP16(dst, src) \
    asm volatile("cp.async.cg.shared.global [%0], [%1], 16;" :: "r"(dst), "l"(src) : "memory")
#define LDMX4(r, addr) \
    asm volatile("ldmatrix.sync.aligned.m8n8.x4.shared.b16 {%0,%1,%2,%3}, [%4];" \
                 : "=r"((r)[0]), "=r"((r)[1]), "=r"((r)[2]), "=r"((r)[3]) : "r"(addr))
#define MMA16816(c, a, b0, b1) \
    asm volatile("mma.sync.aligned.m16n8k16.row.col.f32.bf16.bf16.f32 " \
                 "{%0,%1,%2,%3},{%4,%5,%6,%7},{%8,%9},{%0,%1,%2,%3};" \
                 : "+f"((c)[0]), "+f"((c)[1]), "+f"((c)[2]), "+f"((c)[3]) \
                 : "r"((a)[0]), "r"((a)[1]), "r"((a)[2]), "r"((a)[3]), "r"(b0), "r"(b1))

// physical smem offset inside a subtile: 64B rows, segment slot XOR-swizzled
__device__ __forceinline__ uint32_t phys(int row, int s) {
    return (uint32_t)(row * 64 + ((s ^ ((row >> 1) & 3)) << 4));
}

// ---------------------------------------------------------------------------
// prep (all four tensors, one launch):
// fp32 [b][c][p] -> bf16 split [b][p][2K] + sum-of-squares partials
// ---------------------------------------------------------------------------
__global__ void prep_kernel(const float* __restrict__ f0, const float* __restrict__ f1,
                            const float* __restrict__ f2, const float* __restrict__ f3)
{
    __shared__ __nv_bfloat16 tH[32][34], tL[32][34];
    __shared__ float red[8][32];

    int y = blockIdx.y;
    int slot, cblk;
    const float* f;
    if      (y < 32)  { slot = 0; cblk = y;       f = f0; }
    else if (y < 64)  { slot = 1; cblk = y - 32;  f = f1; }
    else if (y < 128) { slot = 2; cblk = y - 64;  f = f2; }
    else              { slot = 3; cblk = y - 128; f = f3; }
    int K = (slot < 2) ? 1024 : 2048;
    __nv_bfloat16* X = (slot == 0) ? g_Xs3 : (slot == 1) ? g_Xt3 :
                       (slot == 2) ? g_Xs4 : g_Xt4;

    int tx = threadIdx.x, ty = threadIdx.y;
    int p0 = blockIdx.x * 32, c0 = cblk * 32, b = blockIdx.z;
    const float* fb = f + (size_t)b * K * HW;

    float sq = 0.f;
    #pragma unroll
    for (int r = 0; r < 4; r++) {
        int c = c0 + ty + 8 * r;
        float v = fb[(size_t)c * HW + p0 + tx];
        __nv_bfloat16 h = __float2bfloat16_rn(v);
        tH[ty + 8 * r][tx] = h;
        tL[ty + 8 * r][tx] = __float2bfloat16_rn(v - __bfloat162float(h));
        sq = fmaf(v, v, sq);
    }
    red[ty][tx] = sq;
    __syncthreads();
    if (ty == 0) {
        float s = 0.f;
        #pragma unroll
        for (int k = 0; k < 8; k++) s += red[k][tx];
        g_part[slot][cblk][b * HW + p0 + tx] = s;
    }
    int K2 = 2 * K;
    #pragma unroll
    for (int r = 0; r < 4; r++) {
        int p = p0 + ty + 8 * r;
        size_t base = ((size_t)(b * HW + p)) * K2 + c0 + tx;
        X[base]     = tH[tx][ty + 8 * r];
        X[base + K] = tL[tx][ty + 8 * r];
    }
}

__global__ void finalize_norm_kernel()
{
    int idx = blockIdx.x * 256 + threadIdx.x;
    if (idx >= 4 * B * HW) return;
    int slot = idx >> 13, p = idx & (B * HW - 1);
    int nb = (slot < 2) ? 32 : 64;
    float s = 0.f;
    for (int k = 0; k < nb; k++) s += g_part[slot][k][p];
    g_inorm[slot][p] = 1.0f / sqrtf(s + 1e-6f);
}

// ---------------------------------------------------------------------------
// HMMA correlation GEMM (bf16x3), k-chunk 32, 3-stage cp.async ring,
// ONE __syncthreads per chunk. Subtile: 128 rows x 64B, XOR-swizzled segments
// -> coalesced 64B global reads, conflict-free stores AND ldmatrix.
// which=0: res3 (K=1024) -> g_M = C
// which=1: res4 (K=2048) -> v = g_M*C; write g_M AND g_MT (smem transpose)
// CTA 128x128, 8 warps (4x2), warp tile 32x64.
// ---------------------------------------------------------------------------
#define SUBT  8192u
#define ST_AH 0u
#define ST_AL SUBT
#define ST_BH (2u * SUBT)
#define ST_BL (3u * SUBT)
#define STAGE (4u * SUBT)          // 32768
#define NSTG  3
#define SMEM_GEMM (NSTG * 32768)   // 98304; epilogue buf 128*129*4=66048 fits

__global__ __launch_bounds__(256, 2) void gemm_hmma_kernel(int which)
{
    extern __shared__ char sm[];
    uint32_t su = smem_u32(sm);

    const int K    = which ? 2048 : 1024;
    const int catW = 2 * K;
    const int slotA = which ? 3 : 1;   // tgt norms (rows j)
    const int slotB = which ? 2 : 0;   // src norms (cols i)
    const __nv_bfloat16* Ap = which ? g_Xt4 : g_Xt3;
    const __nv_bfloat16* Bp = which ? g_Xs4 : g_Xs3;

    int b  = blockIdx.z;
    int i0 = blockIdx.x * 128, j0 = blockIdx.y * 128;
    int tid = threadIdx.x, lane = tid & 31, warp = tid >> 5;
    int wm = warp & 3, wn = warp >> 2;     // j: wm*32, i: wn*64

    const __nv_bfloat16* Ab = Ap + (size_t)(b * HW + j0) * catW;
    const __nv_bfloat16* Bb = Bp + (size_t)(b * HW + i0) * catW;

    // cp.async: op o = tid + 256q; row = o>>2 (0..127), seg = o&3
    // global: 4 lanes = 64B contiguous; smem: swizzled within 64B row
    int row0 = tid >> 2,         s0c = tid & 3;
    int row1 = (tid + 256) >> 2, s1c = tid & 3;
    uint32_t smA0 = phys(row0, s0c), smA1 = phys(row1, s1c);
    const __nv_bfloat16* gA0 = Ab + (size_t)row0 * catW + s0c * 8;
    const __nv_bfloat16* gA1 = Ab + (size_t)row1 * catW + s1c * 8;
    const __nv_bfloat16* gB0 = Bb + (size_t)row0 * catW + s0c * 8;
    const __nv_bfloat16* gB1 = Bb + (size_t)row1 * catW + s1c * 8;

    // ldmatrix lane addresses (per ks in {0,1}): A rows, seg = ks*2 + (lane>>4)
    int aRow = wm * 32 + ((lane >> 3) & 1) * 8 + (lane & 7);
    uint32_t aAddr0 = phys(aRow, (lane >> 4));            // ks=0
    uint32_t aAddr1 = phys(aRow, 2 + (lane >> 4));        // ks=1
    // B rows, seg = ks*2 + ((lane>>3)&1)
    int bRow = wn * 64 + ((lane >> 4) & 1) * 8 + (lane & 7);
    uint32_t bAddr0 = phys(bRow, ((lane >> 3) & 1));
    uint32_t bAddr1 = phys(bRow, 2 + ((lane >> 3) & 1));

    float acc[2][8][4];
    #pragma unroll
    for (int mi = 0; mi < 2; mi++)
        #pragma unroll
        for (int ni = 0; ni < 8; ni++)
            #pragma unroll
            for (int q = 0; q < 4; q++) acc[mi][ni][q] = 0.f;

    const int nch = K >> 5;

    auto loadStage = [&](int ch, int buf) {
        uint32_t st = su + (uint32_t)buf * STAGE;
        int kel = ch * 32;
        CP16(st + ST_AH + smA0, gA0 + kel);
        CP16(st + ST_AH + smA1, gA1 + kel);
        CP16(st + ST_AL + smA0, gA0 + kel + K);
        CP16(st + ST_AL + smA1, gA1 + kel + K);
        CP16(st + ST_BH + smA0, gB0 + kel);
        CP16(st + ST_BH + smA1, gB1 + kel);
        CP16(st + ST_BL + smA0, gB0 + kel + K);
        CP16(st + ST_BL + smA1, gB1 + kel + K);
        asm volatile("cp.async.commit_group;" ::: "memory");
    };

    loadStage(0, 0);
    loadStage(1, 1);

    int bufC = 0;                       // ch % NSTG
    int bufL = 2;                       // (ch+2) % NSTG
    for (int ch = 0; ch < nch; ch++) {
        if (ch + 1 < nch) asm volatile("cp.async.wait_group 1;" ::: "memory");
        else              asm volatile("cp.async.wait_group 0;" ::: "memory");
        __syncthreads();
        // ring buffer bufL == (ch-1)%NSTG was consumed at ch-1; fenced by sync
        if (ch + 2 < nch) loadStage(ch + 2, bufL);

        uint32_t st = su + (uint32_t)bufC * STAGE;
        #pragma unroll
        for (int ks = 0; ks < 2; ks++) {
            uint32_t aA = ks ? aAddr1 : aAddr0;
            uint32_t bA = ks ? bAddr1 : bAddr0;
            uint32_t ahi[2][4], alo[2][4], br[4][4];
            LDMX4(ahi[0], st + ST_AH + aA);
            LDMX4(ahi[1], st + ST_AH + aA + 1024u);
            LDMX4(alo[0], st + ST_AL + aA);
            LDMX4(alo[1], st + ST_AL + aA + 1024u);
            #pragma unroll
            for (int np = 0; np < 4; np++)
                LDMX4(br[np], st + ST_BH + bA + np * 1024u);
            #pragma unroll
            for (int mi = 0; mi < 2; mi++)
                #pragma unroll
                for (int ni = 0; ni < 8; ni++)
                    MMA16816(acc[mi][ni], ahi[mi],
                             br[ni >> 1][(ni & 1) * 2], br[ni >> 1][(ni & 1) * 2 + 1]);
            #pragma unroll
            for (int mi = 0; mi < 2; mi++)
                #pragma unroll
                for (int ni = 0; ni < 8; ni++)
                    MMA16816(acc[mi][ni], alo[mi],
                             br[ni >> 1][(ni & 1) * 2], br[ni >> 1][(ni & 1) * 2 + 1]);
            #pragma unroll
            for (int np = 0; np < 4; np++)
                LDMX4(br[np], st + ST_BL + bA + np * 1024u);
            #pragma unroll
            for (int mi = 0; mi < 2; mi++)
                #pragma unroll
                for (int ni = 0; ni < 8; ni++)
                    MMA16816(acc[mi][ni], ahi[mi],
                             br[ni >> 1][(ni & 1) * 2], br[ni >> 1][(ni & 1) * 2 + 1]);
        }
        bufC = (bufC == NSTG - 1) ? 0 : bufC + 1;
        bufL = (bufL == NSTG - 1) ? 0 : bufL + 1;
    }

    // ------------------- epilogue -------------------
    int rl = wm * 32 + (lane >> 2);         // local j
    int cl = wn * 64 + (lane & 3) * 2;      // local i
    int rj = j0 + rl, ci = i0 + cl;

    float sj[2][2], si[8][2];
    #pragma unroll
    for (int mi = 0; mi < 2; mi++) {
        sj[mi][0] = g_inorm[slotA][b * HW + rj + mi * 16];
        sj[mi][1] = g_inorm[slotA][b * HW + rj + mi * 16 + 8];
    }
    #pragma unroll
    for (int ni = 0; ni < 8; ni++) {
        si[ni][0] = g_inorm[slotB][b * HW + ci + ni * 8];
        si[ni][1] = g_inorm[slotB][b * HW + ci + ni * 8 + 1];
    }

    size_t mbase = (size_t)b * HW * HW;
    if (which == 0) {
        #pragma unroll
        for (int mi = 0; mi < 2; mi++)
            #pragma unroll
            for (int ni = 0; ni < 8; ni++) {
                int r = rj + mi * 16, c = ci + ni * 8;
                float v00 = fmaxf(acc[mi][ni][0] * sj[mi][0] * si[ni][0], 0.f);
                float v01 = fmaxf(acc[mi][ni][1] * sj[mi][0] * si[ni][1], 0.f);
                float v10 = fmaxf(acc[mi][ni][2] * sj[mi][1] * si[ni][0], 0.f);
                float v11 = fmaxf(acc[mi][ni][3] * sj[mi][1] * si[ni][1], 0.f);
                *(float2*)&g_M[mbase + (size_t)r * HW + c]       = make_float2(v00, v01);
                *(float2*)&g_M[mbase + (size_t)(r + 8) * HW + c] = make_float2(v10, v11);
            }
    } else {
        __syncthreads();                    // all loads drained; reuse smem
        float* buf = (float*)sm;            // 128 x 129 floats (66 KB)
        #pragma unroll
        for (int mi = 0; mi < 2; mi++)
            #pragma unroll
            for (int ni = 0; ni < 8; ni++) {
                int r = rj + mi * 16, c = ci + ni * 8;
                int lr = rl + mi * 16, lc = cl + ni * 8;
                float v00 = fmaxf(acc[mi][ni][0] * sj[mi][0] * si[ni][0], 0.f);
                float v01 = fmaxf(acc[mi][ni][1] * sj[mi][0] * si[ni][1], 0.f);
                float v10 = fmaxf(acc[mi][ni][2] * sj[mi][1] * si[ni][0], 0.f);
                float v11 = fmaxf(acc[mi][ni][3] * sj[mi][1] * si[ni][1], 0.f);
                float2* p0 = (float2*)&g_M[mbase + (size_t)r * HW + c];
                float2* p1 = (float2*)&g_M[mbase + (size_t)(r + 8) * HW + c];
                float2 o0 = *p0, o1 = *p1;
                float w00 = o0.x * v00, w01 = o0.y * v01;
                float w10 = o1.x * v10, w11 = o1.y * v11;
                *p0 = make_float2(w00, w01);
                *p1 = make_float2(w10, w11);
                buf[lr * 129 + lc]           = w00;
                buf[lr * 129 + lc + 1]       = w01;
                buf[(lr + 8) * 129 + lc]     = w10;
                buf[(lr + 8) * 129 + lc + 1] = w11;
            }
        __syncthreads();
        #pragma unroll
        for (int it = 0; it < 16; it++) {
            int c = warp * 16 + it;          // local i (column of tile)
            int r = lane * 4;                // local j
            float4 v;
            v.x = buf[(r + 0) * 129 + c];
            v.y = buf[(r + 1) * 129 + c];
            v.z = buf[(r + 2) * 129 + c];
            v.w = buf[(r + 3) * 129 + c];
            *(float4*)&g_MT[mbase + (size_t)(i0 + c) * HW + j0 + r] = v;
        }
    }
}

// ---------------------------------------------------------------------------
// kernel-soft-argmax, both directions in one launch.
// ---------------------------------------------------------------------------
__global__ __launch_bounds__(256)
void soft_argmax_kernel(float* __restrict__ out)
{
    __shared__ float srow[HW];
    __shared__ float gx[64], gy[64];
    __shared__ float wsum[8], wmax[8], wS[8], wSY[8];
    __shared__ int   widx[8];
    __shared__ float s_alpha;
    __shared__ int   s_xs, s_ys;

    int dir = blockIdx.x >> 13;
    int sub = blockIdx.x & 8191;
    int row = sub & (HW - 1);
    int b   = sub >> 12;
    const float* base = dir ? g_M : g_MT;
    float* outG = out + dir * 32768;
    const float4* rp = (const float4*)(base + (size_t)sub * HW);

    int tid = threadIdx.x, warp = tid >> 5, lane = tid & 31;

    #pragma unroll
    for (int q = 0; q < 4; q++) {
        float4 v = rp[q * 256 + tid];
        *(float4*)&srow[(q * 256 + tid) * 4] = v;
    }
    __syncthreads();

    float sumsq = 0.f, vmax = -1.f;
    int imax = 0;
    #pragma unroll
    for (int q = 0; q < 16; q++) {
        int a = q * 256 + tid;
        float v = srow[a];
        sumsq = fmaf(v, v, sumsq);
        if (v > vmax) { vmax = v; imax = a; }
    }
    #pragma unroll
    for (int off = 16; off > 0; off >>= 1) {
        sumsq += __shfl_down_sync(0xffffffffu, sumsq, off);
        float ov = __shfl_down_sync(0xffffffffu, vmax, off);
        int   oi = __shfl_down_sync(0xffffffffu, imax, off);
        if (ov > vmax || (ov == vmax && oi < imax)) { vmax = ov; imax = oi; }
    }
    if (lane == 0) { wsum[warp] = sumsq; wmax[warp] = vmax; widx[warp] = imax; }
    __syncthreads();
    if (tid == 0) {
        float ss = 0.f, vm = -1.f; int im = 0;
        #pragma unroll
        for (int w = 0; w < 8; w++) {
            ss += wsum[w];
            if (wmax[w] > vm || (wmax[w] == vm && widx[w] < im)) { vm = wmax[w]; im = widx[w]; }
        }
        s_alpha = 50.f / sqrtf(ss + 1e-6f);
        s_xs = im & 63;
        s_ys = im >> 6;
    }
    __syncthreads();

    if (tid < 64) {
        float dx = (float)(tid - s_xs);
        gx[tid] = __expf(-dx * dx * 0.02f);
    } else if (tid < 128) {
        float dy = (float)((tid - 64) - s_ys);
        gy[tid - 64] = __expf(-dy * dy * 0.02f);
    }
    __syncthreads();

    float alpha = s_alpha;
    int   xa  = tid & 63;
    float gxv = gx[xa];
    float xn  = fmaf((float)xa, 2.f / 63.f, -1.f);

    float s = 0.f, sy = 0.f;
    #pragma unroll
    for (int q = 0; q < 16; q++) {
        int a  = q * 256 + tid;
        int ya = a >> 6;
        float e = __expf(alpha * gxv * gy[ya] * srow[a]);
        s += e;
        sy = fmaf(e, fmaf((float)ya, 2.f / 63.f, -1.f), sy);
    }
    float sx = s * xn;

    #pragma unroll
    for (int off = 16; off > 0; off >>= 1) {
        s  += __shfl_down_sync(0xffffffffu, s,  off);
        sx += __shfl_down_sync(0xffffffffu, sx, off);
        sy += __shfl_down_sync(0xffffffffu, sy, off);
    }
    if (lane == 0) { wS[warp] = s; wsum[warp] = sx; wSY[warp] = sy; }
    __syncthreads();
    if (tid == 0) {
        float S = 0.f, SX = 0.f, SY = 0.f;
        #pragma unroll
        for (int w = 0; w < 8; w++) { S += wS[w]; SX += wsum[w]; SY += wSY[w]; }
        int yr = row >> 6, xr = row & 63;
        size_t o = ((size_t)(b * 64 + yr) * 64 + xr) * 2;
        outG[o + 0] = SX / S;
        outG[o + 1] = SY / S;
    }
}

// ---------------------------------------------------------------------------
extern "C" void kernel_launch(void* const* d_in, const int* in_sizes, int n_in,
                              void* d_out, int out_size)
{
    const float* src3 = (const float*)d_in[0];
    const float* tgt3 = (const float*)d_in[1];
    const float* src4 = (const float*)d_in[2];
    const float* tgt4 = (const float*)d_in[3];
    float* out = (float*)d_out;

    cudaFuncSetAttribute(gemm_hmma_kernel,
                         cudaFuncAttributeMaxDynamicSharedMemorySize, SMEM_GEMM);

    prep_kernel<<<dim3(HW / 32, 192, B), dim3(32, 8)>>>(src3, tgt3, src4, tgt4);
    finalize_norm_kernel<<<128, 256>>>();

    dim3 gg(HW / 128, HW / 128, B);
    gemm_hmma_kernel<<<gg, 256, SMEM_GEMM>>>(0);   // res3: M  = C3
    gemm_hmma_kernel<<<gg, 256, SMEM_GEMM>>>(1);   // res4: M *= C4, MT written too

    soft_argmax_kernel<<<2 * B * HW, 256>>>(out);  // both directions

    cudaMemsetAsync(out + 16384, 0, 16384 * sizeof(float));
    cudaMemsetAsync(out + 49152, 0, 16384 * sizeof(float));
}

// round 16
// speedup vs baseline: 1.6979x; 1.0775x over previous
#include <cuda_runtime.h>
#include <cuda_bf16.h>
#include <cstdint>
#include <cstddef>

#define HW 4096
#define B  2

__device__ __align__(128) float g_M [(size_t)B * HW * HW];
__device__ __align__(128) float g_MT[(size_t)B * HW * HW];
// bf16 split features, layout [b][p][2K]: cols [0,K)=hi, [K,2K)=lo (K-major)
__device__ __align__(128) __nv_bfloat16 g_Xs3[(size_t)B * HW * 2048];
__device__ __align__(128) __nv_bfloat16 g_Xt3[(size_t)B * HW * 2048];
__device__ __align__(128) __nv_bfloat16 g_Xs4[(size_t)B * HW * 4096];
__device__ __align__(128) __nv_bfloat16 g_Xt4[(size_t)B * HW * 4096];
__device__ float g_part[4][64][B * HW];
__device__ float g_inorm[4][B * HW];   // 0:src3 1:tgt3 2:src4 3:tgt4

__device__ __forceinline__ uint32_t smem_u32(const void* p) {
    uint32_t a;
    asm("{ .reg .u64 t; cvta.to.shared.u64 t, %1; cvt.u32.u64 %0, t; }" : "=r"(a) : "l"(p));
    return a;
}
#define CP16(dst, src) \
    asm volatile("cp.async.cg.shared.global [%0], [%1], 16;" :: "r"(dst), "l"(src) : "memory")
#define LDMX4(r, addr) \
    asm volatile("ldmatrix.sync.aligned.m8n8.x4.shared.b16 {%0,%1,%2,%3}, [%4];" \
                 : "=r"((r)[0]), "=r"((r)[1]), "=r"((r)[2]), "=r"((r)[3]) : "r"(addr))
#define MMA16816(c, a, b0, b1) \
    asm volatile("mma.sync.aligned.m16n8k16.row.col.f32.bf16.bf16.f32 " \
                 "{%0,%1,%2,%3},{%4,%5,%6,%7},{%8,%9},{%0,%1,%2,%3};" \
                 : "+f"((c)[0]), "+f"((c)[1]), "+f"((c)[2]), "+f"((c)[3]) \
                 : "r"((a)[0]), "r"((a)[1]), "r"((a)[2]), "r"((a)[3]), "r"(b0), "r"(b1))

// physical smem offset inside a subtile: 64B rows, segment slot XOR-swizzled
__device__ __forceinline__ uint32_t phys(int row, int s) {
    return (uint32_t)(row * 64 + ((s ^ ((row >> 1) & 3)) << 4));
}

// ---------------------------------------------------------------------------
// prep (all four tensors, one launch):
// fp32 [b][c][p] -> bf16 split [b][p][2K] + sum-of-squares partials
// ---------------------------------------------------------------------------
__global__ void prep_kernel(const float* __restrict__ f0, const float* __restrict__ f1,
                            const float* __restrict__ f2, const float* __restrict__ f3)
{
    __shared__ __nv_bfloat16 tH[32][34], tL[32][34];
    __shared__ float red[8][32];

    int y = blockIdx.y;
    int slot, cblk;
    const float* f;
    if      (y < 32)  { slot = 0; cblk = y;       f = f0; }
    else if (y < 64)  { slot = 1; cblk = y - 32;  f = f1; }
    else if (y < 128) { slot = 2; cblk = y - 64;  f = f2; }
    else              { slot = 3; cblk = y - 128; f = f3; }
    int K = (slot < 2) ? 1024 : 2048;
    __nv_bfloat16* X = (slot == 0) ? g_Xs3 : (slot == 1) ? g_Xt3 :
                       (slot == 2) ? g_Xs4 : g_Xt4;

    int tx = threadIdx.x, ty = threadIdx.y;
    int p0 = blockIdx.x * 32, c0 = cblk * 32, b = blockIdx.z;
    const float* fb = f + (size_t)b * K * HW;

    float sq = 0.f;
    #pragma unroll
    for (int r = 0; r < 4; r++) {
        int c = c0 + ty + 8 * r;
        float v = fb[(size_t)c * HW + p0 + tx];
        __nv_bfloat16 h = __float2bfloat16_rn(v);
        tH[ty + 8 * r][tx] = h;
        tL[ty + 8 * r][tx] = __float2bfloat16_rn(v - __bfloat162float(h));
        sq = fmaf(v, v, sq);
    }
    red[ty][tx] = sq;
    __syncthreads();
    if (ty == 0) {
        float s = 0.f;
        #pragma unroll
        for (int k = 0; k < 8; k++) s += red[k][tx];
        g_part[slot][cblk][b * HW + p0 + tx] = s;
    }
    int K2 = 2 * K;
    #pragma unroll
    for (int r = 0; r < 4; r++) {
        int p = p0 + ty + 8 * r;
        size_t base = ((size_t)(b * HW + p)) * K2 + c0 + tx;
        X[base]     = tH[tx][ty + 8 * r];
        X[base + K] = tL[tx][ty + 8 * r];
    }
}

__global__ void finalize_norm_kernel()
{
    int idx = blockIdx.x * 256 + threadIdx.x;
    if (idx >= 4 * B * HW) return;
    int slot = idx >> 13, p = idx & (B * HW - 1);
    int nb = (slot < 2) ? 32 : 64;
    float s = 0.f;
    for (int k = 0; k < nb; k++) s += g_part[slot][k][p];
    g_inorm[slot][p] = 1.0f / sqrtf(s + 1e-6f);
}

// ---------------------------------------------------------------------------
// HMMA correlation GEMM (bf16x3), k-chunk 32, 3-stage cp.async ring,
// ONE __syncthreads per chunk, manually scheduled LDSM/MMA interleave.
// Subtile: 128 rows x 64B, XOR-swizzled segments.
// which=0: res3 (K=1024) -> g_M = C
// which=1: res4 (K=2048) -> v = g_M*C; write g_M AND g_MT (smem transpose)
// CTA 128x128, 8 warps (4x2), warp tile 32x64.
// ---------------------------------------------------------------------------
#define SUBT  8192u
#define ST_AH 0u
#define ST_AL SUBT
#define ST_BH (2u * SUBT)
#define ST_BL (3u * SUBT)
#define STAGE (4u * SUBT)          // 32768
#define NSTG  3
#define SMEM_GEMM (NSTG * 32768)   // 98304; epilogue buf 128*129*4=66048 fits

__global__ __launch_bounds__(256, 2) void gemm_hmma_kernel(int which)
{
    extern __shared__ char sm[];
    uint32_t su = smem_u32(sm);

    const int K    = which ? 2048 : 1024;
    const int catW = 2 * K;
    const int slotA = which ? 3 : 1;   // tgt norms (rows j)
    const int slotB = which ? 2 : 0;   // src norms (cols i)
    const __nv_bfloat16* Ap = which ? g_Xt4 : g_Xt3;
    const __nv_bfloat16* Bp = which ? g_Xs4 : g_Xs3;

    int b  = blockIdx.z;
    int i0 = blockIdx.x * 128, j0 = blockIdx.y * 128;
    int tid = threadIdx.x, lane = tid & 31, warp = tid >> 5;
    int wm = warp & 3, wn = warp >> 2;     // j: wm*32, i: wn*64

    const __nv_bfloat16* Ab = Ap + (size_t)(b * HW + j0) * catW;
    const __nv_bfloat16* Bb = Bp + (size_t)(b * HW + i0) * catW;

    // cp.async: op o = tid + 256q; row = o>>2 (0..127), seg = o&3
    int row0 = tid >> 2,         s0c = tid & 3;
    int row1 = (tid + 256) >> 2, s1c = tid & 3;
    uint32_t smA0 = phys(row0, s0c), smA1 = phys(row1, s1c);
    const __nv_bfloat16* gA0 = Ab + (size_t)row0 * catW + s0c * 8;
    const __nv_bfloat16* gA1 = Ab + (size_t)row1 * catW + s1c * 8;
    const __nv_bfloat16* gB0 = Bb + (size_t)row0 * catW + s0c * 8;
    const __nv_bfloat16* gB1 = Bb + (size_t)row1 * catW + s1c * 8;

    // ldmatrix lane addresses (per ks in {0,1})
    int aRow = wm * 32 + ((lane >> 3) & 1) * 8 + (lane & 7);
    uint32_t aAddr0 = phys(aRow, (lane >> 4));
    uint32_t aAddr1 = phys(aRow, 2 + (lane >> 4));
    int bRow = wn * 64 + ((lane >> 4) & 1) * 8 + (lane & 7);
    uint32_t bAddr0 = phys(bRow, ((lane >> 3) & 1));
    uint32_t bAddr1 = phys(bRow, 2 + ((lane >> 3) & 1));

    float acc[2][8][4];
    #pragma unroll
    for (int mi = 0; mi < 2; mi++)
        #pragma unroll
        for (int ni = 0; ni < 8; ni++)
            #pragma unroll
            for (int q = 0; q < 4; q++) acc[mi][ni][q] = 0.f;

    const int nch = K >> 5;

    auto loadStage = [&](int ch, int buf) {
        uint32_t st = su + (uint32_t)buf * STAGE;
        int kel = ch * 32;
        CP16(st + ST_AH + smA0, gA0 + kel);
        CP16(st + ST_AH + smA1, gA1 + kel);
        CP16(st + ST_AL + smA0, gA0 + kel + K);
        CP16(st + ST_AL + smA1, gA1 + kel + K);
        CP16(st + ST_BH + smA0, gB0 + kel);
        CP16(st + ST_BH + smA1, gB1 + kel);
        CP16(st + ST_BL + smA0, gB0 + kel + K);
        CP16(st + ST_BL + smA1, gB1 + kel + K);
        asm volatile("cp.async.commit_group;" ::: "memory");
    };

    // one ks-half of a chunk: hi*hi, lo*hi (with BL rotation), hi*lo
    auto computeKs = [&](uint32_t st, uint32_t aA, uint32_t bA) {
        uint32_t ahi[2][4], alo[2][4], br[4][4];
        LDMX4(ahi[0], st + ST_AH + aA);
        LDMX4(ahi[1], st + ST_AH + aA + 1024u);
        LDMX4(br[0],  st + ST_BH + bA);
        LDMX4(br[1],  st + ST_BH + bA + 1024u);
        LDMX4(br[2],  st + ST_BH + bA + 2048u);
        LDMX4(br[3],  st + ST_BH + bA + 3072u);
        // hi*hi np=0
        MMA16816(acc[0][0], ahi[0], br[0][0], br[0][1]);
        MMA16816(acc[1][0], ahi[1], br[0][0], br[0][1]);
        MMA16816(acc[0][1], ahi[0], br[0][2], br[0][3]);
        MMA16816(acc[1][1], ahi[1], br[0][2], br[0][3]);
        LDMX4(alo[0], st + ST_AL + aA);
        // hi*hi np=1
        MMA16816(acc[0][2], ahi[0], br[1][0], br[1][1]);
        MMA16816(acc[1][2], ahi[1], br[1][0], br[1][1]);
        MMA16816(acc[0][3], ahi[0], br[1][2], br[1][3]);
        MMA16816(acc[1][3], ahi[1], br[1][2], br[1][3]);
        LDMX4(alo[1], st + ST_AL + aA + 1024u);
        // hi*hi np=2,3
        MMA16816(acc[0][4], ahi[0], br[2][0], br[2][1]);
        MMA16816(acc[1][4], ahi[1], br[2][0], br[2][1]);
        MMA16816(acc[0][5], ahi[0], br[2][2], br[2][3]);
        MMA16816(acc[1][5], ahi[1], br[2][2], br[2][3]);
        MMA16816(acc[0][6], ahi[0], br[3][0], br[3][1]);
        MMA16816(acc[1][6], ahi[1], br[3][0], br[3][1]);
        MMA16816(acc[0][7], ahi[0], br[3][2], br[3][3]);
        MMA16816(acc[1][7], ahi[1], br[3][2], br[3][3]);
        // lo*hi, rotating each br[np] to its BL copy right after use
        #pragma unroll
        for (int np = 0; np < 4; np++) {
            MMA16816(acc[0][2*np],   alo[0], br[np][0], br[np][1]);
            MMA16816(acc[1][2*np],   alo[1], br[np][0], br[np][1]);
            MMA16816(acc[0][2*np+1], alo[0], br[np][2], br[np][3]);
            MMA16816(acc[1][2*np+1], alo[1], br[np][2], br[np][3]);
            LDMX4(br[np], st + ST_BL + bA + np * 1024u);
        }
        // hi*lo
        #pragma unroll
        for (int np = 0; np < 4; np++) {
            MMA16816(acc[0][2*np],   ahi[0], br[np][0], br[np][1]);
            MMA16816(acc[1][2*np],   ahi[1], br[np][0], br[np][1]);
            MMA16816(acc[0][2*np+1], ahi[0], br[np][2], br[np][3]);
            MMA16816(acc[1][2*np+1], ahi[1], br[np][2], br[np][3]);
        }
    };

    loadStage(0, 0);
    loadStage(1, 1);

    int bufC = 0;                       // ch % NSTG
    int bufL = 2;                       // (ch+2) % NSTG
    for (int ch = 0; ch < nch; ch++) {
        if (ch + 1 < nch) asm volatile("cp.async.wait_group 1;" ::: "memory");
        else              asm volatile("cp.async.wait_group 0;" ::: "memory");
        __syncthreads();

        uint32_t st = su + (uint32_t)bufC * STAGE;
        computeKs(st, aAddr0, bAddr0);              // ks = 0 (LDSM first!)
        if (ch + 2 < nch) loadStage(ch + 2, bufL);  // cp.async mid-chunk
        computeKs(st, aAddr1, bAddr1);              // ks = 1

        bufC = (bufC == NSTG - 1) ? 0 : bufC + 1;
        bufL = (bufL == NSTG - 1) ? 0 : bufL + 1;
    }

    // ------------------- epilogue -------------------
    int rl = wm * 32 + (lane >> 2);         // local j
    int cl = wn * 64 + (lane & 3) * 2;      // local i
    int rj = j0 + rl, ci = i0 + cl;

    float sj[2][2], si[8][2];
    #pragma unroll
    for (int mi = 0; mi < 2; mi++) {
        sj[mi][0] = g_inorm[slotA][b * HW + rj + mi * 16];
        sj[mi][1] = g_inorm[slotA][b * HW + rj + mi * 16 + 8];
    }
    #pragma unroll
    for (int ni = 0; ni < 8; ni++) {
        si[ni][0] = g_inorm[slotB][b * HW + ci + ni * 8];
        si[ni][1] = g_inorm[slotB][b * HW + ci + ni * 8 + 1];
    }

    size_t mbase = (size_t)b * HW * HW;
    if (which == 0) {
        #pragma unroll
        for (int mi = 0; mi < 2; mi++)
            #pragma unroll
            for (int ni = 0; ni < 8; ni++) {
                int r = rj + mi * 16, c = ci + ni * 8;
                float v00 = fmaxf(acc[mi][ni][0] * sj[mi][0] * si[ni][0], 0.f);
                float v01 = fmaxf(acc[mi][ni][1] * sj[mi][0] * si[ni][1], 0.f);
                float v10 = fmaxf(acc[mi][ni][2] * sj[mi][1] * si[ni][0], 0.f);
                float v11 = fmaxf(acc[mi][ni][3] * sj[mi][1] * si[ni][1], 0.f);
                *(float2*)&g_M[mbase + (size_t)r * HW + c]       = make_float2(v00, v01);
                *(float2*)&g_M[mbase + (size_t)(r + 8) * HW + c] = make_float2(v10, v11);
            }
    } else {
        __syncthreads();                    // all loads drained; reuse smem
        float* buf = (float*)sm;            // 128 x 129 floats (66 KB)
        #pragma unroll
        for (int mi = 0; mi < 2; mi++)
            #pragma unroll
            for (int ni = 0; ni < 8; ni++) {
                int r = rj + mi * 16, c = ci + ni * 8;
                int lr = rl + mi * 16, lc = cl + ni * 8;
                float v00 = fmaxf(acc[mi][ni][0] * sj[mi][0] * si[ni][0], 0.f);
                float v01 = fmaxf(acc[mi][ni][1] * sj[mi][0] * si[ni][1], 0.f);
                float v10 = fmaxf(acc[mi][ni][2] * sj[mi][1] * si[ni][0], 0.f);
                float v11 = fmaxf(acc[mi][ni][3] * sj[mi][1] * si[ni][1], 0.f);
                float2* p0 = (float2*)&g_M[mbase + (size_t)r * HW + c];
                float2* p1 = (float2*)&g_M[mbase + (size_t)(r + 8) * HW + c];
                float2 o0 = *p0, o1 = *p1;
                float w00 = o0.x * v00, w01 = o0.y * v01;
                float w10 = o1.x * v10, w11 = o1.y * v11;
                *p0 = make_float2(w00, w01);
                *p1 = make_float2(w10, w11);
                buf[lr * 129 + lc]           = w00;
                buf[lr * 129 + lc + 1]       = w01;
                buf[(lr + 8) * 129 + lc]     = w10;
                buf[(lr + 8) * 129 + lc + 1] = w11;
            }
        __syncthreads();
        #pragma unroll
        for (int it = 0; it < 16; it++) {
            int c = warp * 16 + it;          // local i (column of tile)
            int r = lane * 4;                // local j
            float4 v;
            v.x = buf[(r + 0) * 129 + c];
            v.y = buf[(r + 1) * 129 + c];
            v.z = buf[(r + 2) * 129 + c];
            v.w = buf[(r + 3) * 129 + c];
            *(float4*)&g_MT[mbase + (size_t)(i0 + c) * HW + j0 + r] = v;
        }
    }
}

// ---------------------------------------------------------------------------
// kernel-soft-argmax, both directions in one launch.
// ---------------------------------------------------------------------------
__global__ __launch_bounds__(256)
void soft_argmax_kernel(float* __restrict__ out)
{
    __shared__ float srow[HW];
    __shared__ float gx[64], gy[64];
    __shared__ float wsum[8], wmax[8], wS[8], wSY[8];
    __shared__ int   widx[8];
    __shared__ float s_alpha;
    __shared__ int   s_xs, s_ys;

    int dir = blockIdx.x >> 13;
    int sub = blockIdx.x & 8191;
    int row = sub & (HW - 1);
    int b   = sub >> 12;
    const float* base = dir ? g_M : g_MT;
    float* outG = out + dir * 32768;
    const float4* rp = (const float4*)(base + (size_t)sub * HW);

    int tid = threadIdx.x, warp = tid >> 5, lane = tid & 31;

    #pragma unroll
    for (int q = 0; q < 4; q++) {
        float4 v = rp[q * 256 + tid];
        *(float4*)&srow[(q * 256 + tid) * 4] = v;
    }
    __syncthreads();

    float sumsq = 0.f, vmax = -1.f;
    int imax = 0;
    #pragma unroll
    for (int q = 0; q < 16; q++) {
        int a = q * 256 + tid;
        float v = srow[a];
        sumsq = fmaf(v, v, sumsq);
        if (v > vmax) { vmax = v; imax = a; }
    }
    #pragma unroll
    for (int off = 16; off > 0; off >>= 1) {
        sumsq += __shfl_down_sync(0xffffffffu, sumsq, off);
        float ov = __shfl_down_sync(0xffffffffu, vmax, off);
        int   oi = __shfl_down_sync(0xffffffffu, imax, off);
        if (ov > vmax || (ov == vmax && oi < imax)) { vmax = ov; imax = oi; }
    }
    if (lane == 0) { wsum[warp] = sumsq; wmax[warp] = vmax; widx[warp] = imax; }
    __syncthreads();
    if (tid == 0) {
        float ss = 0.f, vm = -1.f; int im = 0;
        #pragma unroll
        for (int w = 0; w < 8; w++) {
            ss += wsum[w];
            if (wmax[w] > vm || (wmax[w] == vm && widx[w] < im)) { vm = wmax[w]; im = widx[w]; }
        }
        s_alpha = 50.f / sqrtf(ss + 1e-6f);
        s_xs = im & 63;
        s_ys = im >> 6;
    }
    __syncthreads();

    if (tid < 64) {
        float dx = (float)(tid - s_xs);
        gx[tid] = __expf(-dx * dx * 0.02f);
    } else if (tid < 128) {
        float dy = (float)((tid - 64) - s_ys);
        gy[tid - 64] = __expf(-dy * dy * 0.02f);
    }
    __syncthreads();

    float alpha = s_alpha;
    int   xa  = tid & 63;
    float gxv = gx[xa];
    float xn  = fmaf((float)xa, 2.f / 63.f, -1.f);

    float s = 0.f, sy = 0.f;
    #pragma unroll
    for (int q = 0; q < 16; q++) {
        int a  = q * 256 + tid;
        int ya = a >> 6;
        float e = __expf(alpha * gxv * gy[ya] * srow[a]);
        s += e;
        sy = fmaf(e, fmaf((float)ya, 2.f / 63.f, -1.f), sy);
    }
    float sx = s * xn;

    #pragma unroll
    for (int off = 16; off > 0; off >>= 1) {
        s  += __shfl_down_sync(0xffffffffu, s,  off);
        sx += __shfl_down_sync(0xffffffffu, sx, off);
        sy += __shfl_down_sync(0xffffffffu, sy, off);
    }
    if (lane == 0) { wS[warp] = s; wsum[warp] = sx; wSY[warp] = sy; }
    __syncthreads();
    if (tid == 0) {
        float S = 0.f, SX = 0.f, SY = 0.f;
        #pragma unroll
        for (int w = 0; w < 8; w++) { S += wS[w]; SX += wsum[w]; SY += wSY[w]; }
        int yr = row >> 6, xr = row & 63;
        size_t o = ((size_t)(b * 64 + yr) * 64 + xr) * 2;
        outG[o + 0] = SX / S;
        outG[o + 1] = SY / S;
    }
}

// ---------------------------------------------------------------------------
extern "C" void kernel_launch(void* const* d_in, const int* in_sizes, int n_in,
                              void* d_out, int out_size)
{
    const float* src3 = (const float*)d_in[0];
    const float* tgt3 = (const float*)d_in[1];
    const float* src4 = (const float*)d_in[2];
    const float* tgt4 = (const float*)d_in[3];
    float* out = (float*)d_out;

    cudaFuncSetAttribute(gemm_hmma_kernel,
                         cudaFuncAttributeMaxDynamicSharedMemorySize, SMEM_GEMM);

    prep_kernel<<<dim3(HW / 32, 192, B), dim3(32, 8)>>>(src3, tgt3, src4, tgt4);
    finalize_norm_kernel<<<128, 256>>>();

    dim3 gg(HW / 128, HW / 128, B);
    gemm_hmma_kernel<<<gg, 256, SMEM_GEMM>>>(0);   // res3: M  = C3
    gemm_hmma_kernel<<<gg, 256, SMEM_GEMM>>>(1);   // res4: M *= C4, MT written too

    soft_argmax_kernel<<<2 * B * HW, 256>>>(out);  // both directions

    cudaMemsetAsync(out + 16384, 0, 16384 * sizeof(float));
    cudaMemsetAsync(out + 49152, 0, 16384 * sizeof(float));
}